// round 17
// baseline (speedup 1.0000x reference)
#include <cuda_runtime.h>
#include <mma.h>
#include <cstdint>

using namespace nvcuda;

// Problem constants
#define NPART 8
#define B_    8
#define H_    256
#define W_    512
#define CI_   32
#define CO_   32
#define HP_   32
#define NTAPS 13

#define THREADS 256
#define TCOLS   64            // output cols per block
#define TROWS   4             // output rows per block
#define XT_ROWS 6             // staged input rows (y0-2 .. y0+3)
#define XT_COLS 68            // staged cols (x0-2 .. x0+65)
#define XT_STRIDE 36          // floats per (row,col) pixel: 32 ci + pad (144B)

#define SMEM_FLOATS (XT_ROWS * XT_COLS * XT_STRIDE)   // 14688
#define SMEM_BYTES  (SMEM_FLOATS * 4)                 // 58752 -> 3 blocks/SM

#define SCR_STRIDE 260        // epilogue scratch: [co][260] (256 pixels + pad)

// Masked weights, tf32-rounded, layout [tap][kchunk(4)][k(8)][co(32)]
__device__ float g_wB[NTAPS * 4 * 8 * CO_];

// ---------------------------------------------------------------------------
// Prep: PixelCNN group mask (HIDDEN: center visible iff gin<=gout), tf32 round.
// tap: 0-4 = (ky0,kx0-4), 5-9 = (ky1,kx0-4), 10-12 = (ky2,kx0-2; kx2 gated)
// ---------------------------------------------------------------------------
__global__ void prep_weights(const float* __restrict__ w) {
    int i = blockIdx.x * blockDim.x + threadIdx.x;
    if (i >= NTAPS * 4 * 8 * CO_) return;
    int co  = i & 31;
    int k   = (i >> 5) & 7;
    int kc  = (i >> 8) & 3;
    int tap = i >> 10;
    int ci  = kc * 8 + k;
    int ky  = (tap < 5) ? 0 : (tap < 10 ? 1 : 2);
    int kx  = tap - (ky == 0 ? 0 : (ky == 1 ? 5 : 10));
    float m = 1.0f;
    if (ky == 2 && kx == 2)
        m = ((ci >> 2) <= (co >> 2)) ? 1.0f : 0.0f;
    float val = w[((co * CI_ + ci) * 5 + ky) * 5 + kx] * m;
    g_wB[i] = wmma::__float_to_tf32(val);
}

// ---------------------------------------------------------------------------
// Main kernel. Grid: (W/64=8, H/4=64, B=8). Block: 256 threads (8 warps).
// Warp tile: 16 output cols x 16 co x 4 output rows (4 accumulators).
// ---------------------------------------------------------------------------
extern __shared__ float sX[];   // [6][68][36] input (tf32), reused as scratch

__global__ void __launch_bounds__(THREADS)
conv_kernel(const float* __restrict__ x,
            const float* __restrict__ bias,
            const float* __restrict__ alpha,
            const int*   __restrict__ widths,
            float* __restrict__ out)
{
    const int x0    = blockIdx.x * TCOLS;
    const int y0    = blockIdx.y * TROWS;
    const int b     = blockIdx.z;
    const int part  = y0 >> 5;
    const int width = widths[part];

    const int tid  = threadIdx.x;
    const int warp = tid >> 5;
    const int lane = tid & 31;

    // ---- fast path: whole tile beyond valid width -> zeros ----
    if (x0 >= width) {
        #pragma unroll
        for (int e = tid; e < TROWS * TCOLS * CO_; e += THREADS) {
            int col = e & 63;
            int row = (e >> 6) & 3;
            int co  = e >> 8;
            out[((size_t)(b * CO_ + co) * H_ + y0 + row) * W_ + x0 + col] = 0.f;
        }
        return;
    }

    // ---- stage input tile (masked, tf32-rounded, coalesced reads) ----
    {
        const int wlim = (width < W_) ? width : W_;
        const int ysl  = part * HP_;
        const int ylb  = (y0 & 31) - 2;
        #pragma unroll
        for (int p = warp; p < XT_ROWS * CI_; p += 8) {
            const int irow = p >> 5;             // 0..5
            const int ci   = p & 31;
            const int ly   = ylb + irow;
            const bool rowok = (ly >= 0) && (ly < HP_);
            const float* grow = x + ((size_t)(b * CI_ + ci) * H_ + (ysl + ly)) * W_;
            int g0 = x0 - 2 + lane;
            int g1 = g0 + 32;
            float v0 = 0.f, v1 = 0.f;
            if (rowok) {
                if (g0 >= 0 && g0 < wlim) v0 = wmma::__float_to_tf32(grow[g0]);
                if (g1 < wlim)            v1 = wmma::__float_to_tf32(grow[g1]);
            }
            sX[(irow * XT_COLS + lane)      * XT_STRIDE + ci] = v0;
            sX[(irow * XT_COLS + lane + 32) * XT_STRIDE + ci] = v1;
            if (lane < 4) {
                int g2 = g0 + 64;
                float v2 = (rowok && g2 < wlim) ? wmma::__float_to_tf32(grow[g2]) : 0.f;
                sX[(irow * XT_COLS + lane + 64) * XT_STRIDE + ci] = v2;
            }
        }
    }
    __syncthreads();

    // ---- warp tile assignment ----
    const int c0 = (warp >> 1) * 16;     // output col base (0/16/32/48)
    const int h0 = (warp & 1) * 16;      // co base (0/16)

    wmma::fragment<wmma::accumulator, 16, 16, 8, float> acc[TROWS];
    #pragma unroll
    for (int r = 0; r < TROWS; ++r) wmma::fill_fragment(acc[r], 0.0f);

    if (x0 + c0 < width) {               // warp-level width skip
        #pragma unroll 1
        for (int tap = 0; tap < NTAPS; ++tap) {
            const int ky = (tap < 5) ? 0 : (tap < 10 ? 1 : 2);
            const int kx = tap - (ky == 0 ? 0 : (ky == 1 ? 5 : 10));
            const float* abase = sX + (ky * XT_COLS + (c0 + kx)) * XT_STRIDE;
            #pragma unroll
            for (int kc = 0; kc < 4; ++kc) {
                wmma::fragment<wmma::matrix_b, 16, 16, 8,
                               wmma::precision::tf32, wmma::row_major> bf;
                wmma::load_matrix_sync(bf, g_wB + ((tap * 4 + kc) * 8) * CO_ + h0, CO_);
                #pragma unroll
                for (int r = 0; r < TROWS; ++r) {
                    wmma::fragment<wmma::matrix_a, 16, 16, 8,
                                   wmma::precision::tf32, wmma::row_major> af;
                    wmma::load_matrix_sync(
                        af, abase + r * (XT_COLS * XT_STRIDE) + kc * 8, XT_STRIDE);
                    wmma::mma_sync(acc[r], af, bf, acc[r]);
                }
            }
        }
    }

    // ---- dump accumulators to smem scratch (col-major: [co][pixel]) ----
    __syncthreads();                      // all warps done reading sX
    float* scr = sX;                      // reuse: 32 * 260 = 8320 floats
    #pragma unroll
    for (int r = 0; r < TROWS; ++r)
        wmma::store_matrix_sync(scr + h0 * SCR_STRIDE + (r * 64 + c0), acc[r],
                                SCR_STRIDE, wmma::mem_col_major);
    __syncthreads();

    // ---- epilogue: bias, leaky-ReLU, width mask; coalesced stores ----
    #pragma unroll
    for (int e = tid; e < TROWS * TCOLS * CO_; e += THREADS) {
        int col = e & 63;
        int row = (e >> 6) & 3;
        int co  = e >> 8;
        float v = scr[co * SCR_STRIDE + row * 64 + col];
        float y = v + __ldg(bias + co);
        float a = __ldg(alpha + co);
        y = (y > 0.f) ? y : a * y;
        int gx = x0 + col;
        out[((size_t)(b * CO_ + co) * H_ + y0 + row) * W_ + gx] =
            (gx < width) ? y : 0.f;
    }
}

// ---------------------------------------------------------------------------
// Launch
// ---------------------------------------------------------------------------
extern "C" void kernel_launch(void* const* d_in, const int* in_sizes, int n_in,
                              void* d_out, int out_size)
{
    const float* x      = (const float*)d_in[0];
    const float* weight = (const float*)d_in[1];
    const float* bias   = (const float*)d_in[2];
    const float* alpha  = (const float*)d_in[3];
    const int*   widths = (const int*)  d_in[4];
    float* out = (float*)d_out;

    (void)in_sizes; (void)n_in; (void)out_size;

    cudaFuncSetAttribute(conv_kernel,
                         cudaFuncAttributeMaxDynamicSharedMemorySize,
                         SMEM_BYTES);

    prep_weights<<<(NTAPS * 4 * 8 * CO_ + 255) / 256, 256>>>(weight);

    dim3 grid(W_ / TCOLS, H_ / TROWS, B_);
    conv_kernel<<<grid, THREADS, SMEM_BYTES>>>(x, bias, alpha, widths, out);
}